// round 14
// baseline (speedup 1.0000x reference)
#include <cuda_runtime.h>

#define D 128
#define H 8
#define MAXN 50000
#define MAXE 800000

// ---- scratch (static device globals; no allocation allowed) ----
__device__ float g_q[MAXN * D];
__device__ float g_k[MAXN * D];
__device__ float g_v[MAXN * D];
__device__ float g_agg[MAXN * D];
__device__ int   g_deg[MAXN];
__device__ int   g_rowptr[MAXN + 1];
__device__ int   g_cursor[MAXN];
__device__ int   g_src[MAXE];                  // source node r per CSR slot

// ============================================================================
// Packed-f32x2 helpers (FFMA2 via PTX fma.rn.f32x2)
// ============================================================================
__device__ __forceinline__ void fma2(unsigned long long& d,
                                     unsigned long long a,
                                     unsigned long long b) {
    asm("fma.rn.f32x2 %0, %1, %2, %0;" : "+l"(d) : "l"(a), "l"(b));
}
__device__ __forceinline__ unsigned long long pack2(float x) {
    unsigned long long r;
    asm("mov.b64 %0, {%1, %1};" : "=l"(r) : "f"(x));
    return r;
}
__device__ __forceinline__ void unpack2(unsigned long long d, float& lo, float& hi) {
    asm("mov.b64 {%0, %1}, %2;" : "=f"(lo), "=f"(hi) : "l"(d));
}

// ============================================================================
// GEMM tile body: C[bm..bm+128, :] = A[rows] @ W^T + bias
// BM=128, BN=128, BK=16, 256 threads, FFMA2 inner product.
// Double-buffered smem, register prefetch, ONE __syncthreads per K-slab.
// ============================================================================
__device__ __forceinline__ void gemm_tile(
    const float* __restrict__ A, const float* __restrict__ W,
    const float* __restrict__ bias, float* __restrict__ C, int M, int bm)
{
    __shared__ __align__(16) float sA[2][16][132];
    __shared__ __align__(16) float sW[2][16][132];

    const int tid = threadIdx.x;
    const int tx  = tid & 15;      // col-pair group: cols 2*tx + 32*jp (+0/+1)
    const int ty  = tid >> 4;      // row group: rows ty + 16*i
    const int lr  = tid >> 1;      // load row 0..127
    const int lc  = (tid & 1) * 8; // load col offset within 16-wide K slab

    const int   grow  = bm + lr;
    const bool  rowok = (grow < M);
    const float* Arow = A + (size_t)grow * D + lc;
    const float* Wrow = W + (size_t)lr * D + lc;

    unsigned long long acc[8][4];
#pragma unroll
    for (int i = 0; i < 8; i++)
#pragma unroll
        for (int j = 0; j < 4; j++) acc[i][j] = 0ull;

    // prologue: load slab 0 into buffer 0
    {
        float4 a0 = make_float4(0.f,0.f,0.f,0.f), a1 = a0;
        if (rowok) { a0 = *(const float4*)(Arow); a1 = *(const float4*)(Arow + 4); }
        const float4 w0 = *(const float4*)(Wrow);
        const float4 w1 = *(const float4*)(Wrow + 4);
        sA[0][lc+0][lr]=a0.x; sA[0][lc+1][lr]=a0.y; sA[0][lc+2][lr]=a0.z; sA[0][lc+3][lr]=a0.w;
        sA[0][lc+4][lr]=a1.x; sA[0][lc+5][lr]=a1.y; sA[0][lc+6][lr]=a1.z; sA[0][lc+7][lr]=a1.w;
        sW[0][lc+0][lr]=w0.x; sW[0][lc+1][lr]=w0.y; sW[0][lc+2][lr]=w0.z; sW[0][lc+3][lr]=w0.w;
        sW[0][lc+4][lr]=w1.x; sW[0][lc+5][lr]=w1.y; sW[0][lc+6][lr]=w1.z; sW[0][lc+7][lr]=w1.w;
    }
    __syncthreads();

    int cur = 0;
#pragma unroll
    for (int k0 = 16; k0 < D; k0 += 16) {
        // prefetch next slab (LDGs issued before the FFMA block)
        float4 a0 = make_float4(0.f,0.f,0.f,0.f), a1 = a0;
        if (rowok) { a0 = *(const float4*)(Arow + k0); a1 = *(const float4*)(Arow + k0 + 4); }
        const float4 w0 = *(const float4*)(Wrow + k0);
        const float4 w1 = *(const float4*)(Wrow + k0 + 4);

        // compute current slab
#pragma unroll
        for (int kk = 0; kk < 16; kk++) {
            unsigned long long ad[8], wd[4];
#pragma unroll
            for (int i = 0; i < 8; i++) ad[i] = pack2(sA[cur][kk][ty + i * 16]);
#pragma unroll
            for (int jp = 0; jp < 4; jp++)
                wd[jp] = *(const unsigned long long*)&sW[cur][kk][2 * tx + 32 * jp];
#pragma unroll
            for (int i = 0; i < 8; i++)
#pragma unroll
                for (int jp = 0; jp < 4; jp++)
                    fma2(acc[i][jp], ad[i], wd[jp]);
        }

        // store prefetched slab into the other buffer
        const int nxt = cur ^ 1;
        sA[nxt][lc+0][lr]=a0.x; sA[nxt][lc+1][lr]=a0.y; sA[nxt][lc+2][lr]=a0.z; sA[nxt][lc+3][lr]=a0.w;
        sA[nxt][lc+4][lr]=a1.x; sA[nxt][lc+5][lr]=a1.y; sA[nxt][lc+6][lr]=a1.z; sA[nxt][lc+7][lr]=a1.w;
        sW[nxt][lc+0][lr]=w0.x; sW[nxt][lc+1][lr]=w0.y; sW[nxt][lc+2][lr]=w0.z; sW[nxt][lc+3][lr]=w0.w;
        sW[nxt][lc+4][lr]=w1.x; sW[nxt][lc+5][lr]=w1.y; sW[nxt][lc+6][lr]=w1.z; sW[nxt][lc+7][lr]=w1.w;

        __syncthreads();   // publishes nxt AND protects cur from next overwrite
        cur = nxt;
    }

    // epilogue slab
#pragma unroll
    for (int kk = 0; kk < 16; kk++) {
        unsigned long long ad[8], wd[4];
#pragma unroll
        for (int i = 0; i < 8; i++) ad[i] = pack2(sA[cur][kk][ty + i * 16]);
#pragma unroll
        for (int jp = 0; jp < 4; jp++)
            wd[jp] = *(const unsigned long long*)&sW[cur][kk][2 * tx + 32 * jp];
#pragma unroll
        for (int i = 0; i < 8; i++)
#pragma unroll
            for (int jp = 0; jp < 4; jp++)
                fma2(acc[i][jp], ad[i], wd[jp]);
    }

    float2 bv[4];
#pragma unroll
    for (int jp = 0; jp < 4; jp++)
        bv[jp] = *(const float2*)&bias[2 * tx + 32 * jp];

#pragma unroll
    for (int i = 0; i < 8; i++) {
        const int row = bm + ty + i * 16;
        if (row >= M) continue;
#pragma unroll
        for (int jp = 0; jp < 4; jp++) {
            float lo, hi;
            unpack2(acc[i][jp], lo, hi);
            *(float2*)&C[(size_t)row * D + 2 * tx + 32 * jp] =
                make_float2(lo + bv[jp].x, hi + bv[jp].y);
        }
    }
}

// ============================================================================
// CSR stage bodies
// ============================================================================
__device__ __forceinline__ void deg_body(const int* __restrict__ ei, int E, int b)
{
    const int base = (b * 256 + threadIdx.x) * 8;   // 8 edges per thread
    if (base >= E) return;
#pragma unroll
    for (int t = 0; t < 4; t++) {
        const int e = base + t * 2;
        if (e < E) {
            const int4 p = ((const int4*)ei)[e >> 1];   // {r0,c0,r1,c1}
            atomicAdd(&g_deg[p.y], 1);
            if (e + 1 < E) atomicAdd(&g_deg[p.w], 1);
        }
    }
}

__device__ __forceinline__ void scatter_body(const int* __restrict__ ei, int E, int b)
{
    const int base = (b * 256 + threadIdx.x) * 8;
    if (base >= E) return;
#pragma unroll
    for (int t = 0; t < 4; t++) {
        const int e = base + t * 2;
        if (e < E) {
            const int4 p = ((const int4*)ei)[e >> 1];
            g_src[atomicAdd(&g_cursor[p.y], 1)] = p.x;
            if (e + 1 < E) g_src[atomicAdd(&g_cursor[p.w], 1)] = p.z;
        }
    }
}

// 256-thread exclusive scan: rowptr + cursor seed. chunk-per-thread + shfl scan.
__device__ __forceinline__ void scan_body(int N, int E)
{
    __shared__ int warp_sums[8];
    const int tid   = threadIdx.x;
    const int chunk = (N + 255) / 256;
    const int lo    = tid * chunk;
    const int hi    = min(lo + chunk, N);

    int sum = 0;
    for (int i = lo; i < hi; i++) sum += g_deg[i];

    const int lane = tid & 31, wid = tid >> 5;
    int val = sum;
#pragma unroll
    for (int off = 1; off < 32; off <<= 1) {
        const int n = __shfl_up_sync(0xffffffffu, val, off);
        if (lane >= off) val += n;
    }
    if (lane == 31) warp_sums[wid] = val;
    __syncthreads();
    if (wid == 0 && lane < 8) {
        int w = warp_sums[lane];
#pragma unroll
        for (int off = 1; off < 8; off <<= 1) {
            const int n = __shfl_up_sync(0xffu, w, off);
            if (lane >= off) w += n;
        }
        warp_sums[lane] = w;
    }
    __syncthreads();

    int run = val - sum + (wid > 0 ? warp_sums[wid - 1] : 0);  // exclusive prefix
    for (int i = lo; i < hi; i++) {
        const int d = g_deg[i];
        g_rowptr[i] = run; g_cursor[i] = run;
        run += d;
    }
    if (tid == 0) g_rowptr[N] = E;
}

// ============================================================================
// Fat kernels: GEMM blocks [0, gblocks), CSR-stage blocks [gblocks, ...)
// ============================================================================
__global__ __launch_bounds__(256) void k_gemm_deg(
    const float* __restrict__ A, const float* __restrict__ W,
    const float* __restrict__ bias, float* __restrict__ C, int M, int gblocks,
    const int* __restrict__ ei, int E)
{
    if ((int)blockIdx.x < gblocks) gemm_tile(A, W, bias, C, M, blockIdx.x * 128);
    else                           deg_body(ei, E, blockIdx.x - gblocks);
}

__global__ __launch_bounds__(256) void k_gemm_scan(
    const float* __restrict__ A, const float* __restrict__ W,
    const float* __restrict__ bias, float* __restrict__ C, int M, int gblocks,
    int N, int E)
{
    if ((int)blockIdx.x < gblocks)           gemm_tile(A, W, bias, C, M, blockIdx.x * 128);
    else if ((int)blockIdx.x == gblocks)     scan_body(N, E);
}

__global__ __launch_bounds__(256) void k_gemm_scatter(
    const float* __restrict__ A, const float* __restrict__ W,
    const float* __restrict__ bias, float* __restrict__ C, int M, int gblocks,
    const int* __restrict__ ei, int E)
{
    if ((int)blockIdx.x < gblocks) gemm_tile(A, W, bias, C, M, blockIdx.x * 128);
    else                           scatter_body(ei, E, blockIdx.x - gblocks);
}

__global__ __launch_bounds__(256) void gemm_bias_kernel(
    const float* __restrict__ A, const float* __restrict__ W,
    const float* __restrict__ bias, float* __restrict__ C, int M)
{
    gemm_tile(A, W, bias, C, M, blockIdx.x * 128);
}

// ============================================================================
// Fused single-pass per-node attention: one warp per destination node.
// attn = exp(s)/(sum exp(si) + 1)  (max-shift cancels identically).
// 2-edge software pipeline, dual accumulators, __ldg gathers.
// (R9 configuration: 47 regs, occ ~49% — measured 71.0 us, at LTS floor.)
// ============================================================================
__global__ __launch_bounds__(256) void node_attn_kernel(int N)
{
    const int nid  = blockIdx.x * 8 + (threadIdx.x >> 5);
    const int lane = threadIdx.x & 31;
    if (nid >= N) return;

    const int start = g_rowptr[nid];
    const int end   = g_rowptr[nid + 1];
    const int deg   = end - start;

    const float4 qv = __ldg(((const float4*)g_q) + nid * 32 + lane);

    float4 acc0 = make_float4(0.f, 0.f, 0.f, 0.f);
    float4 acc1 = make_float4(0.f, 0.f, 0.f, 0.f);
    float d0 = 0.0f, d1 = 0.0f;

    for (int base = start; base < end; base += 32) {
        const int nb = min(32, end - base);
        int my_src = 0;
        if (base + lane < end) my_src = g_src[base + lane];

        int t = 0;
#pragma unroll 2
        for (; t + 2 <= nb; t += 2) {
            const int r0 = __shfl_sync(0xffffffffu, my_src, t);
            const int r1 = __shfl_sync(0xffffffffu, my_src, t + 1);
            const float4 k0 = __ldg(((const float4*)g_k) + r0 * 32 + lane);
            const float4 v0 = __ldg(((const float4*)g_v) + r0 * 32 + lane);
            const float4 k1 = __ldg(((const float4*)g_k) + r1 * 32 + lane);
            const float4 v1 = __ldg(((const float4*)g_v) + r1 * 32 + lane);

            float s0 = k0.x * qv.x + k0.y * qv.y + k0.z * qv.z + k0.w * qv.w;
            float s1 = k1.x * qv.x + k1.y * qv.y + k1.z * qv.z + k1.w * qv.w;
            s0 += __shfl_xor_sync(0xffffffffu, s0, 1);
            s1 += __shfl_xor_sync(0xffffffffu, s1, 1);
            s0 += __shfl_xor_sync(0xffffffffu, s0, 2);
            s1 += __shfl_xor_sync(0xffffffffu, s1, 2);

            const float e0 = __expf(s0 * 0.25f);
            const float e1 = __expf(s1 * 0.25f);
            acc0.x = fmaf(e0, v0.x, acc0.x); acc1.x = fmaf(e1, v1.x, acc1.x);
            acc0.y = fmaf(e0, v0.y, acc0.y); acc1.y = fmaf(e1, v1.y, acc1.y);
            acc0.z = fmaf(e0, v0.z, acc0.z); acc1.z = fmaf(e1, v1.z, acc1.z);
            acc0.w = fmaf(e0, v0.w, acc0.w); acc1.w = fmaf(e1, v1.w, acc1.w);
            d0 += e0; d1 += e1;
        }
        if (t < nb) {
            const int r0 = __shfl_sync(0xffffffffu, my_src, t);
            const float4 k0 = __ldg(((const float4*)g_k) + r0 * 32 + lane);
            const float4 v0 = __ldg(((const float4*)g_v) + r0 * 32 + lane);
            float s0 = k0.x * qv.x + k0.y * qv.y + k0.z * qv.z + k0.w * qv.w;
            s0 += __shfl_xor_sync(0xffffffffu, s0, 1);
            s0 += __shfl_xor_sync(0xffffffffu, s0, 2);
            const float e0 = __expf(s0 * 0.25f);
            acc0.x = fmaf(e0, v0.x, acc0.x);
            acc0.y = fmaf(e0, v0.y, acc0.y);
            acc0.z = fmaf(e0, v0.z, acc0.z);
            acc0.w = fmaf(e0, v0.w, acc0.w);
            d0 += e0;
        }
    }

    const float scale = 1.0f / ((d0 + d1 + 1.0f) * (float)max(deg, 1));
    float4 outv;
    outv.x = (acc0.x + acc1.x) * scale;
    outv.y = (acc0.y + acc1.y) * scale;
    outv.z = (acc0.z + acc1.z) * scale;
    outv.w = (acc0.w + acc1.w) * scale;
    ((float4*)g_agg)[nid * 32 + lane] = outv;
}

// ============================================================================
// Launch
// ============================================================================
extern "C" void kernel_launch(void* const* d_in, const int* in_sizes, int n_in,
                              void* d_out, int out_size)
{
    const float* feats = (const float*)d_in[0];
    const int*   ei    = (const int*)d_in[1];
    const float* Wq = (const float*)d_in[2]; const float* bq = (const float*)d_in[3];
    const float* Wk = (const float*)d_in[4]; const float* bk = (const float*)d_in[5];
    const float* Wv = (const float*)d_in[6]; const float* bv = (const float*)d_in[7];
    const float* Wo = (const float*)d_in[8]; const float* bo = (const float*)d_in[9];
    float* out = (float*)d_out;

    const int N = in_sizes[0] / D;
    const int E = in_sizes[1] / 2;

    float *q, *k, *v, *agg;
    int *deg;
    cudaGetSymbolAddress((void**)&q,   g_q);
    cudaGetSymbolAddress((void**)&k,   g_k);
    cudaGetSymbolAddress((void**)&v,   g_v);
    cudaGetSymbolAddress((void**)&agg, g_agg);
    cudaGetSymbolAddress((void**)&deg, g_deg);

    cudaMemsetAsync(deg, 0, (size_t)N * sizeof(int));

    const int gblocks = (N + 127) / 128;
    const int eb8     = (E + 2047) / 2048;   // 8 edges/thread, 256 threads

    k_gemm_deg    <<<gblocks + eb8, 256>>>(feats, Wq, bq, q, N, gblocks, ei, E);
    k_gemm_scan   <<<gblocks + 1,   256>>>(feats, Wk, bk, k, N, gblocks, N, E);
    k_gemm_scatter<<<gblocks + eb8, 256>>>(feats, Wv, bv, v, N, gblocks, ei, E);

    node_attn_kernel<<<(N + 7) / 8, 256>>>(N);

    gemm_bias_kernel<<<gblocks, 256>>>(agg, Wo, bo, out, N);
}

// round 17
// speedup vs baseline: 1.3240x; 1.3240x over previous
#include <cuda_runtime.h>
#include <cuda_bf16.h>
#include <cstdint>

#define D 128
#define H 8
#define MAXN 50000
#define MAXE 800000

// ---- scratch (static device globals; no allocation allowed) ----
__device__ float g_q[MAXN * D];
__device__ float g_k[MAXN * D];
__device__ float g_v[MAXN * D];
__device__ float g_agg[MAXN * D];
__device__ int   g_deg[MAXN];
__device__ int   g_rowptr[MAXN + 1];
__device__ int   g_cursor[MAXN];
__device__ int   g_src[MAXE];

// ============================================================================
// bf16x3 warp-level mma.sync GEMM  (C = A @ W^T + bias)
// 128x128 tile per CTA, 256 threads = 8 warps (2x4 grid, m64n32 per warp),
// K chunked at 64. smem: Ahi/Alo/Whi/Wlo tiles, 128 rows x stride 72 bf16.
// Stride 72 => frag LDS banks = 4*g + t : conflict-free.
// ============================================================================
static constexpr int      KC      = 64;        // K chunk
static constexpr int      SWE     = 72;        // smem row stride (bf16 elems)
static constexpr unsigned TILE_E  = 128 * SWE; // elems per tile
static constexpr unsigned SMEM_BYTES = 4 * TILE_E * 2;   // 73728 B

__device__ __forceinline__ void mma16816(float* c, const uint32_t* a,
                                         const uint32_t* b) {
    asm volatile(
        "mma.sync.aligned.m16n8k16.row.col.f32.bf16.bf16.f32 "
        "{%0,%1,%2,%3}, {%4,%5,%6,%7}, {%8,%9}, {%0,%1,%2,%3};"
        : "+f"(c[0]), "+f"(c[1]), "+f"(c[2]), "+f"(c[3])
        : "r"(a[0]), "r"(a[1]), "r"(a[2]), "r"(a[3]), "r"(b[0]), "r"(b[1]));
}
__device__ __forceinline__ void split2(float x, float y, uint32_t& h, uint32_t& l) {
    __nv_bfloat16 hx = __float2bfloat16_rn(x), hy = __float2bfloat16_rn(y);
    __nv_bfloat16 lx = __float2bfloat16_rn(x - __bfloat162float(hx));
    __nv_bfloat16 ly = __float2bfloat16_rn(y - __bfloat162float(hy));
    __nv_bfloat162 hp(hx, hy), lp(lx, ly);
    h = *reinterpret_cast<uint32_t*>(&hp);
    l = *reinterpret_cast<uint32_t*>(&lp);
}

__device__ void mma_gemm_tile(
    const float* __restrict__ A, const float* __restrict__ W,
    const float* __restrict__ bias, float* __restrict__ C, int M, int bm,
    char* sm)
{
    const int tid  = threadIdx.x;
    const int lane = tid & 31;
    const int w    = tid >> 5;
    const int wm   = w & 1;        // 2 m-blocks of 64
    const int wn   = w >> 1;       // 4 n-blocks of 32
    const int g    = lane >> 2;    // group 0..7
    const int tq   = lane & 3;     // thread-in-group

    __nv_bfloat16* sAhi = (__nv_bfloat16*)sm;
    __nv_bfloat16* sAlo = sAhi + TILE_E;
    __nv_bfloat16* sWhi = sAhi + 2 * TILE_E;
    __nv_bfloat16* sWlo = sAhi + 3 * TILE_E;

    float acc[4][4][4];
#pragma unroll
    for (int i = 0; i < 4; i++)
#pragma unroll
        for (int j = 0; j < 4; j++)
#pragma unroll
            for (int r = 0; r < 4; r++) acc[i][j][r] = 0.0f;

    for (int ch = 0; ch < 2; ch++) {
        if (ch) __syncthreads();   // all frag reads of prev chunk done

        // ---- load + split chunk: 1024 slots = 128 rows x 8 col-groups ----
#pragma unroll
        for (int i = 0; i < 4; i++) {
            const int idx = tid + 256 * i;
            const int row = idx >> 3;
            const int k8  = (idx & 7) * 8;
            const int gk  = ch * KC + k8;
            const size_t sb = (size_t)row * SWE + k8;   // elem offset

            const int grow = bm + row;
            float4 f0 = make_float4(0.f,0.f,0.f,0.f), f1 = f0;
            if (grow < M) {
                f0 = *(const float4*)(A + (size_t)grow * D + gk);
                f1 = *(const float4*)(A + (size_t)grow * D + gk + 4);
            }
            uint4 hi, lo;
            split2(f0.x, f0.y, hi.x, lo.x); split2(f0.z, f0.w, hi.y, lo.y);
            split2(f1.x, f1.y, hi.z, lo.z); split2(f1.z, f1.w, hi.w, lo.w);
            *(uint4*)(sAhi + sb) = hi;
            *(uint4*)(sAlo + sb) = lo;

            const float4 w0 = *(const float4*)(W + (size_t)row * D + gk);
            const float4 w1 = *(const float4*)(W + (size_t)row * D + gk + 4);
            split2(w0.x, w0.y, hi.x, lo.x); split2(w0.z, w0.w, hi.y, lo.y);
            split2(w1.x, w1.y, hi.z, lo.z); split2(w1.z, w1.w, hi.w, lo.w);
            *(uint4*)(sWhi + sb) = hi;
            *(uint4*)(sWlo + sb) = lo;
        }
        __syncthreads();

        // ---- mma over 4 k-steps of 16 ----
#pragma unroll
        for (int ks = 0; ks < 4; ks++) {
            const int k0 = ks * 16 + tq * 2;

            uint32_t ah[4][4], al[4][4];
#pragma unroll
            for (int mf = 0; mf < 4; mf++) {
                const size_t o = (size_t)(wm * 64 + mf * 16 + g) * SWE + k0;
                ah[mf][0] = *(const uint32_t*)(sAhi + o);
                ah[mf][1] = *(const uint32_t*)(sAhi + o + 8 * SWE);
                ah[mf][2] = *(const uint32_t*)(sAhi + o + 8);
                ah[mf][3] = *(const uint32_t*)(sAhi + o + 8 * SWE + 8);
                al[mf][0] = *(const uint32_t*)(sAlo + o);
                al[mf][1] = *(const uint32_t*)(sAlo + o + 8 * SWE);
                al[mf][2] = *(const uint32_t*)(sAlo + o + 8);
                al[mf][3] = *(const uint32_t*)(sAlo + o + 8 * SWE + 8);
            }
#pragma unroll
            for (int nf = 0; nf < 4; nf++) {
                const size_t o = (size_t)(wn * 32 + nf * 8 + g) * SWE + k0;
                uint32_t bh[2], bl[2];
                bh[0] = *(const uint32_t*)(sWhi + o);
                bh[1] = *(const uint32_t*)(sWhi + o + 8);
                bl[0] = *(const uint32_t*)(sWlo + o);
                bl[1] = *(const uint32_t*)(sWlo + o + 8);
#pragma unroll
                for (int mf = 0; mf < 4; mf++) {
                    mma16816(acc[mf][nf], ah[mf], bh);
                    mma16816(acc[mf][nf], ah[mf], bl);
                    mma16816(acc[mf][nf], al[mf], bh);
                }
            }
        }
    }

    // ---- epilogue: fragments -> gmem with bias ----
#pragma unroll
    for (int nf = 0; nf < 4; nf++) {
        const int j = wn * 32 + nf * 8 + tq * 2;
        const float2 bb = *(const float2*)&bias[j];
#pragma unroll
        for (int mf = 0; mf < 4; mf++) {
            const int m0 = bm + wm * 64 + mf * 16 + g;
            if (m0 < M)
                *(float2*)&C[(size_t)m0 * D + j] =
                    make_float2(acc[mf][nf][0] + bb.x, acc[mf][nf][1] + bb.y);
            if (m0 + 8 < M)
                *(float2*)&C[(size_t)(m0 + 8) * D + j] =
                    make_float2(acc[mf][nf][2] + bb.x, acc[mf][nf][3] + bb.y);
        }
    }
}

// ============================================================================
// CSR stage bodies (256-thread blocks, 2048 edges/block)
// ============================================================================
__device__ __forceinline__ void deg_body(const int* __restrict__ ei, int E, int b)
{
    const int base = (b * 256 + threadIdx.x) * 8;
    if (base >= E) return;
#pragma unroll
    for (int t = 0; t < 4; t++) {
        const int e = base + t * 2;
        if (e < E) {
            const int4 p = ((const int4*)ei)[e >> 1];
            atomicAdd(&g_deg[p.y], 1);
            if (e + 1 < E) atomicAdd(&g_deg[p.w], 1);
        }
    }
}
__device__ __forceinline__ void scatter_body(const int* __restrict__ ei, int E, int b)
{
    const int base = (b * 256 + threadIdx.x) * 8;
    if (base >= E) return;
#pragma unroll
    for (int t = 0; t < 4; t++) {
        const int e = base + t * 2;
        if (e < E) {
            const int4 p = ((const int4*)ei)[e >> 1];
            g_src[atomicAdd(&g_cursor[p.y], 1)] = p.x;
            if (e + 1 < E) g_src[atomicAdd(&g_cursor[p.w], 1)] = p.z;
        }
    }
}
__device__ __forceinline__ void scan_body(int N, int E)
{
    __shared__ int warp_sums[8];
    const int tid   = threadIdx.x;
    const int chunk = (N + 255) / 256;
    const int lo    = tid * chunk;
    const int hi    = min(lo + chunk, N);

    int sum = 0;
    for (int i = lo; i < hi; i++) sum += g_deg[i];

    const int lane = tid & 31, wid = tid >> 5;
    int val = sum;
#pragma unroll
    for (int off = 1; off < 32; off <<= 1) {
        const int n = __shfl_up_sync(0xffffffffu, val, off);
        if (lane >= off) val += n;
    }
    if (lane == 31) warp_sums[wid] = val;
    __syncthreads();
    if (wid == 0 && lane < 8) {
        int w = warp_sums[lane];
#pragma unroll
        for (int off = 1; off < 8; off <<= 1) {
            const int n = __shfl_up_sync(0xffu, w, off);
            if (lane >= off) w += n;
        }
        warp_sums[lane] = w;
    }
    __syncthreads();

    int run = val - sum + (wid > 0 ? warp_sums[wid - 1] : 0);
    for (int i = lo; i < hi; i++) {
        const int d = g_deg[i];
        g_rowptr[i] = run; g_cursor[i] = run;
        run += d;
    }
    if (tid == 0) g_rowptr[N] = E;
}

// ============================================================================
// Fat kernels: GEMM blocks [0, gblocks), CSR blocks after
// ============================================================================
extern __shared__ char k_dynsmem[];

__global__ __launch_bounds__(256, 2) void k_gemm_deg(
    const float* __restrict__ A, const float* __restrict__ W,
    const float* __restrict__ bias, float* __restrict__ C, int M, int gblocks,
    const int* __restrict__ ei, int E)
{
    if ((int)blockIdx.x < gblocks)
        mma_gemm_tile(A, W, bias, C, M, blockIdx.x * 128, k_dynsmem);
    else
        deg_body(ei, E, blockIdx.x - gblocks);
}
__global__ __launch_bounds__(256, 2) void k_gemm_scan(
    const float* __restrict__ A, const float* __restrict__ W,
    const float* __restrict__ bias, float* __restrict__ C, int M, int gblocks,
    int N, int E)
{
    if ((int)blockIdx.x < gblocks)
        mma_gemm_tile(A, W, bias, C, M, blockIdx.x * 128, k_dynsmem);
    else if ((int)blockIdx.x == gblocks)
        scan_body(N, E);
}
__global__ __launch_bounds__(256, 2) void k_gemm_scatter(
    const float* __restrict__ A, const float* __restrict__ W,
    const float* __restrict__ bias, float* __restrict__ C, int M, int gblocks,
    const int* __restrict__ ei, int E)
{
    if ((int)blockIdx.x < gblocks)
        mma_gemm_tile(A, W, bias, C, M, blockIdx.x * 128, k_dynsmem);
    else
        scatter_body(ei, E, blockIdx.x - gblocks);
}
__global__ __launch_bounds__(256, 2) void gemm_bias_kernel(
    const float* __restrict__ A, const float* __restrict__ W,
    const float* __restrict__ bias, float* __restrict__ C, int M)
{
    mma_gemm_tile(A, W, bias, C, M, blockIdx.x * 128, k_dynsmem);
}

// ============================================================================
// Fused single-pass per-node attention (R9 config, measured 71-72 us)
// ============================================================================
__global__ __launch_bounds__(256) void node_attn_kernel(int N)
{
    const int nid  = blockIdx.x * 8 + (threadIdx.x >> 5);
    const int lane = threadIdx.x & 31;
    if (nid >= N) return;

    const int start = g_rowptr[nid];
    const int end   = g_rowptr[nid + 1];
    const int deg   = end - start;

    const float4 qv = __ldg(((const float4*)g_q) + nid * 32 + lane);

    float4 acc0 = make_float4(0.f, 0.f, 0.f, 0.f);
    float4 acc1 = make_float4(0.f, 0.f, 0.f, 0.f);
    float d0 = 0.0f, d1 = 0.0f;

    for (int base = start; base < end; base += 32) {
        const int nb = min(32, end - base);
        int my_src = 0;
        if (base + lane < end) my_src = g_src[base + lane];

        int t = 0;
#pragma unroll 2
        for (; t + 2 <= nb; t += 2) {
            const int r0 = __shfl_sync(0xffffffffu, my_src, t);
            const int r1 = __shfl_sync(0xffffffffu, my_src, t + 1);
            const float4 k0 = __ldg(((const float4*)g_k) + r0 * 32 + lane);
            const float4 v0 = __ldg(((const float4*)g_v) + r0 * 32 + lane);
            const float4 k1 = __ldg(((const float4*)g_k) + r1 * 32 + lane);
            const float4 v1 = __ldg(((const float4*)g_v) + r1 * 32 + lane);

            float s0 = k0.x * qv.x + k0.y * qv.y + k0.z * qv.z + k0.w * qv.w;
            float s1 = k1.x * qv.x + k1.y * qv.y + k1.z * qv.z + k1.w * qv.w;
            s0 += __shfl_xor_sync(0xffffffffu, s0, 1);
            s1 += __shfl_xor_sync(0xffffffffu, s1, 1);
            s0 += __shfl_xor_sync(0xffffffffu, s0, 2);
            s1 += __shfl_xor_sync(0xffffffffu, s1, 2);

            const float e0 = __expf(s0 * 0.25f);
            const float e1 = __expf(s1 * 0.25f);
            acc0.x = fmaf(e0, v0.x, acc0.x); acc1.x = fmaf(e1, v1.x, acc1.x);
            acc0.y = fmaf(e0, v0.y, acc0.y); acc1.y = fmaf(e1, v1.y, acc1.y);
            acc0.z = fmaf(e0, v0.z, acc0.z); acc1.z = fmaf(e1, v1.z, acc1.z);
            acc0.w = fmaf(e0, v0.w, acc0.w); acc1.w = fmaf(e1, v1.w, acc1.w);
            d0 += e0; d1 += e1;
        }
        if (t < nb) {
            const int r0 = __shfl_sync(0xffffffffu, my_src, t);
            const float4 k0 = __ldg(((const float4*)g_k) + r0 * 32 + lane);
            const float4 v0 = __ldg(((const float4*)g_v) + r0 * 32 + lane);
            float s0 = k0.x * qv.x + k0.y * qv.y + k0.z * qv.z + k0.w * qv.w;
            s0 += __shfl_xor_sync(0xffffffffu, s0, 1);
            s0 += __shfl_xor_sync(0xffffffffu, s0, 2);
            const float e0 = __expf(s0 * 0.25f);
            acc0.x = fmaf(e0, v0.x, acc0.x);
            acc0.y = fmaf(e0, v0.y, acc0.y);
            acc0.z = fmaf(e0, v0.z, acc0.z);
            acc0.w = fmaf(e0, v0.w, acc0.w);
            d0 += e0;
        }
    }

    const float scale = 1.0f / ((d0 + d1 + 1.0f) * (float)max(deg, 1));
    float4 outv;
    outv.x = (acc0.x + acc1.x) * scale;
    outv.y = (acc0.y + acc1.y) * scale;
    outv.z = (acc0.z + acc1.z) * scale;
    outv.w = (acc0.w + acc1.w) * scale;
    ((float4*)g_agg)[nid * 32 + lane] = outv;
}

// ============================================================================
// Launch
// ============================================================================
extern "C" void kernel_launch(void* const* d_in, const int* in_sizes, int n_in,
                              void* d_out, int out_size)
{
    const float* feats = (const float*)d_in[0];
    const int*   ei    = (const int*)d_in[1];
    const float* Wq = (const float*)d_in[2]; const float* bq = (const float*)d_in[3];
    const float* Wk = (const float*)d_in[4]; const float* bk = (const float*)d_in[5];
    const float* Wv = (const float*)d_in[6]; const float* bv = (const float*)d_in[7];
    const float* Wo = (const float*)d_in[8]; const float* bo = (const float*)d_in[9];
    float* out = (float*)d_out;

    const int N = in_sizes[0] / D;
    const int E = in_sizes[1] / 2;

    float *q, *k, *v, *agg;
    int *deg;
    cudaGetSymbolAddress((void**)&q,   g_q);
    cudaGetSymbolAddress((void**)&k,   g_k);
    cudaGetSymbolAddress((void**)&v,   g_v);
    cudaGetSymbolAddress((void**)&agg, g_agg);
    cudaGetSymbolAddress((void**)&deg, g_deg);

    cudaFuncSetAttribute(k_gemm_deg,      cudaFuncAttributeMaxDynamicSharedMemorySize, SMEM_BYTES);
    cudaFuncSetAttribute(k_gemm_scan,     cudaFuncAttributeMaxDynamicSharedMemorySize, SMEM_BYTES);
    cudaFuncSetAttribute(k_gemm_scatter,  cudaFuncAttributeMaxDynamicSharedMemorySize, SMEM_BYTES);
    cudaFuncSetAttribute(gemm_bias_kernel, cudaFuncAttributeMaxDynamicSharedMemorySize, SMEM_BYTES);

    cudaMemsetAsync(deg, 0, (size_t)N * sizeof(int));

    const int gblocks = (N + 127) / 128;
    const int eb8     = (E + 2047) / 2048;

    k_gemm_deg    <<<gblocks + eb8, 256, SMEM_BYTES>>>(feats, Wq, bq, q, N, gblocks, ei, E);
    k_gemm_scan   <<<gblocks + 1,   256, SMEM_BYTES>>>(feats, Wk, bk, k, N, gblocks, N, E);
    k_gemm_scatter<<<gblocks + eb8, 256, SMEM_BYTES>>>(feats, Wv, bv, v, N, gblocks, ei, E);

    node_attn_kernel<<<(N + 7) / 8, 256>>>(N);

    gemm_bias_kernel<<<gblocks, 256, SMEM_BYTES>>>(agg, Wo, bo, out, N);
}